// round 6
// baseline (speedup 1.0000x reference)
#include <cuda_runtime.h>
#include <math.h>
#include <stdint.h>

#define BATCH   128
#define TT      504
#define TF      502
#define TC      500
#define NSTEP   2000
#define NT      512
#define BPC     4
#define NCTA    (BATCH / BPC)

// ---------------- transposed-weight offsets (floats) ----------------
#define OFF_FWC    0          // (192,328)
#define OFF_FWCG   62976      // (192,192)
#define OFF_G1IH   99840      // (480,272)
#define OFF_G1HH   230400     // (480,160)
#define OFF_GLU1   307200     // (160,160)
#define OFF_G2IH   332800     // (384,240)
#define OFF_G2HH   424960     // (384,128)
#define OFF_GLU2   474112     // (128,128)
#define OFF_G3IH   490496     // (384,208)
#define OFF_G3HH   570368     // (384,128)
#define OFF_GLU3   619520     // (128,128)
#define OFF_SKIP   635904     // (128,688)
#define OFF_SKIPG  723968     // (128,128)
#define OFF_SIG    740352     // (40,128)
#define OFF_GOUT   745472     // (4,192)
#define WT_TOTAL   746240

// sub-block offsets (rows of transposed [in][out] matrices)
#define OFF_G1P   (OFF_G1IH + 192 * 480)
#define OFF_G1V   (OFF_G1IH + 232 * 480)
#define OFF_G2P   (OFF_G2IH + 160 * 384)
#define OFF_G2V   (OFF_G2IH + 200 * 384)
#define OFF_G3P   (OFF_G3IH + 128 * 384)
#define OFF_G3V   (OFF_G3IH + 168 * 384)
#define OFF_SK1   (OFF_SKIP + 0)
#define OFF_SK2   (OFF_SKIP + 160 * 128)
#define OFF_SK3   (OFF_SKIP + 288 * 128)
#define OFF_SKF   (OFF_SKIP + 416 * 128)
#define OFF_SKP   (OFF_SKIP + 608 * 128)
#define OFF_SKV   (OFF_SKIP + 648 * 128)

// ---------------- device scratch ----------------
__device__ float g_x[BATCH * TF * 64];
__device__ float g_cond[BATCH * TC * 320];
__device__ float g_gain[NSTEP * BATCH];
__device__ float g_wt[WT_TOTAL];

__device__ __forceinline__ float sigf(float x) { return 1.0f / (1.0f + expf(-x)); }

typedef unsigned long long u64;
__device__ __forceinline__ u64 pk2(float lo, float hi) {
    u64 r; asm("mov.b64 %0, {%1, %2};" : "=l"(r) : "f"(lo), "f"(hi)); return r;
}
__device__ __forceinline__ u64 dup2(float v) {
    u64 r; asm("mov.b64 %0, {%1, %1};" : "=l"(r) : "f"(v)); return r;
}
__device__ __forceinline__ void fma2(u64& d, u64 a, u64 b) {
    asm("fma.rn.f32x2 %0, %1, %2, %3;" : "=l"(d) : "l"(a), "l"(b), "l"(d));
}
__device__ __forceinline__ float2 upk(u64 v) {
    float2 r; asm("mov.b64 {%0, %1}, %2;" : "=f"(r.x), "=f"(r.y) : "l"(v)); return r;
}
__device__ __forceinline__ float4 add4(float4 a, float4 b) {
    return make_float4(a.x + b.x, a.y + b.y, a.z + b.z, a.w + b.w);
}
__device__ __forceinline__ float4 mul4(float4 a, float4 b) {
    return make_float4(a.x * b.x, a.y * b.y, a.z * b.z, a.w * b.w);
}
__device__ __forceinline__ float4 sig4v(float4 a) {
    return make_float4(sigf(a.x), sigf(a.y), sigf(a.z), sigf(a.w));
}
__device__ __forceinline__ float4 tanh4v(float4 a) {
    return make_float4(tanhf(a.x), tanhf(a.y), tanhf(a.z), tanhf(a.w));
}

// ---------------- fused weight transpose ----------------
struct WP { const float* p[15]; };
__constant__ int T_OFF[15] = {OFF_FWC, OFF_FWCG, OFF_G1IH, OFF_G1HH, OFF_GLU1,
                              OFF_G2IH, OFF_G2HH, OFF_GLU2, OFF_G3IH, OFF_G3HH,
                              OFF_GLU3, OFF_SKIP, OFF_SKIPG, OFF_SIG, OFF_GOUT};
__constant__ int T_OUT[15] = {192, 192, 480, 480, 160, 384, 384, 128, 384, 384, 128, 128, 128, 40, 4};
__constant__ int T_IN [15] = {328, 192, 272, 160, 160, 240, 128, 128, 208, 128, 128, 688, 128, 128, 192};

__global__ void k_transpose_all(WP wp) {
    int l = blockIdx.y;
    int i = blockIdx.x * blockDim.x + threadIdx.x;
    int out = T_OUT[l], in = T_IN[l];
    if (i < out * in) {
        int o = i / in, k = i - o * in;
        g_wt[T_OFF[l] + k * out + o] = wp.p[l][i];
    }
}

// ---------------- fd1 ----------------
__global__ void k_fd1(const float* __restrict__ feat, const int* __restrict__ period,
                      const float* __restrict__ pembed, const float* __restrict__ fd1) {
    int bt = blockIdx.x;
    int b = bt / TF, t = bt - b * TF;
    __shared__ float xin[32];
    int tid = threadIdx.x;
    if (tid < 20) {
        xin[tid] = feat[(b * TT + (t + 2)) * 20 + tid];
    } else if (tid < 32) {
        int per = period[b * TT + t + 2];
        per = min(max(per, 32), 254);
        xin[tid] = pembed[(per - 32) * 12 + (tid - 20)];
    }
    __syncthreads();
    float acc = 0.0f;
    const float* w = fd1 + tid * 32;
#pragma unroll
    for (int k = 0; k < 32; k++) acc += w[k] * xin[k];
    g_x[bt * 64 + tid] = tanhf(acc);
}

// ---------------- fused conv1d + fd2 + gain ----------------
__global__ void k_front(const float* __restrict__ wconv, const float* __restrict__ fd2,
                        const float* __restrict__ cg_w, const float* __restrict__ cg_b) {
    int bt = blockIdx.x;
    int b = bt / TC, t = bt - b * TC;
    __shared__ float xin[192];
    __shared__ float ybuf[128];
    __shared__ float condb[320];
    int tid = threadIdx.x;
    for (int i = tid; i < 192; i += 320) {
        xin[i] = g_x[(b * TF + t + (i >> 6)) * 64 + (i & 63)];
    }
    __syncthreads();
    if (tid < 128) {
        float acc = 0.0f;
        const float* w = wconv + tid * 192;
#pragma unroll 8
        for (int ic = 0; ic < 64; ic++) {
            acc += w[ic * 3 + 0] * xin[0 * 64 + ic];
            acc += w[ic * 3 + 1] * xin[1 * 64 + ic];
            acc += w[ic * 3 + 2] * xin[2 * 64 + ic];
        }
        ybuf[tid] = tanhf(acc);
    }
    __syncthreads();
    {
        float acc = 0.0f;
        const float* w = fd2 + tid * 128;
#pragma unroll 8
        for (int k = 0; k < 128; k++) acc += __ldg(w + k) * ybuf[k];
        float c = tanhf(acc);
        condb[tid] = c;
        g_cond[(size_t)bt * 320 + tid] = c;
    }
    __syncthreads();
    if (tid < 4) {
        float acc = cg_b[0];
        const float* c = condb + tid * 80;
#pragma unroll 8
        for (int k = 0; k < 80; k++) acc += cg_w[k] * c[k];
        float g = 0.2f + 0.8f * sigf(acc);
        g = fminf(fmaxf(g, 0.001f), 20.0f);
        g_gain[(t * 4 + tid) * BATCH + b] = g;
    }
}

// ---------------- task context ----------------
struct Ctx {
    const float4 *skf, *sk1, *sk2, *skp, *skv, *pgv;
    const float* bias;
    const float* gain;
    float* excp;
    float* outp;
    int base, step, b0;
};

// ---------------- generic warp-task matvec segment ----------------
// Wt [IN][OUT] transposed; x float4 batch-packed; warp task = 8 output-f4-groups x 4 k-slices.
// ACT: 0 none, 1 tanh, 2 glu(aux*sig), 3 skip-sum+tanh, 4 pg sigmoid+bias, 5 sig-out (exc/out write)
template <int IN, int OUT, int ACT>
__device__ __forceinline__ void run_seg(int& tb, const float* __restrict__ Wt,
                                        const float4* __restrict__ x,
                                        float4* __restrict__ y,
                                        const float4* __restrict__ aux,
                                        const Ctx& c) {
    constexpr int RG = OUT / 4;
    constexpr int NTASK = (RG + 7) / 8;
    const int wid = threadIdx.x >> 5, lane = threadIdx.x & 31;
    const int sl = lane >> 3, g = lane & 7;
    const float4* __restrict__ W4 = reinterpret_cast<const float4*>(Wt);
    for (int t = (wid - tb) & 15; t < NTASK; t += 16) {
        int group = t * 8 + g;
        int gc = (group < RG) ? group : (RG - 1);
        u64 a[8];
#pragma unroll
        for (int i = 0; i < 8; i++) a[i] = 0ull;
#pragma unroll 8
        for (int k = sl; k < IN; k += 4) {
            float4 xv = x[k];
            u64 x01 = pk2(xv.x, xv.y), x23 = pk2(xv.z, xv.w);
            float4 w = __ldg(&W4[k * RG + gc]);
            u64 w0 = dup2(w.x), w1 = dup2(w.y), w2 = dup2(w.z), w3 = dup2(w.w);
            fma2(a[0], w0, x01); fma2(a[1], w0, x23);
            fma2(a[2], w1, x01); fma2(a[3], w1, x23);
            fma2(a[4], w2, x01); fma2(a[5], w2, x23);
            fma2(a[6], w3, x01); fma2(a[7], w3, x23);
        }
        float r[16];
#pragma unroll
        for (int i = 0; i < 8; i++) { float2 f = upk(a[i]); r[2 * i] = f.x; r[2 * i + 1] = f.y; }
        // r[4o + b] = output o, batch b
#pragma unroll
        for (int i = 0; i < 16; i++) {
            r[i] += __shfl_xor_sync(0xffffffffu, r[i], 8);
            r[i] += __shfl_xor_sync(0xffffffffu, r[i], 16);
        }
        if (sl == 0 && group < RG) {
#pragma unroll
            for (int o = 0; o < 4; o++) {
                int oi = group * 4 + o;
                float4 v = make_float4(r[4 * o], r[4 * o + 1], r[4 * o + 2], r[4 * o + 3]);
                if (ACT == 0) {
                    y[oi] = v;
                } else if (ACT == 1) {
                    y[oi] = tanh4v(v);
                } else if (ACT == 2) {
                    y[oi] = mul4(aux[oi], sig4v(v));
                } else if (ACT == 3) {
                    float4 pg3 = c.pgv[3];
                    float4 t2 = add4(v, add4(c.skf[oi], add4(c.sk1[oi],
                               add4(c.sk2[oi], add4(mul4(pg3, c.skp[oi]), c.skv[oi])))));
                    y[oi] = tanh4v(t2);
                } else if (ACT == 4) {
                    float b = c.bias[oi];
                    y[oi] = sig4v(make_float4(v.x + b, v.y + b, v.z + b, v.w + b));
                } else if (ACT == 5) {
                    float4 vt = tanh4v(v);
                    float4 sg = make_float4(vt.x * c.gain[0], vt.y * c.gain[1],
                                            vt.z * c.gain[2], vt.w * c.gain[3]);
                    int pj = (c.base + oi) & 255;
                    c.excp[0 * 256 + pj] = sg.x;
                    c.excp[1 * 256 + pj] = sg.y;
                    c.excp[2 * 256 + pj] = sg.z;
                    c.excp[3 * 256 + pj] = sg.w;
                    size_t ob = (size_t)c.b0 * 80000 + (size_t)c.step * 40 + oi;
                    c.outp[ob] = sg.x;
                    c.outp[ob + 80000] = sg.y;
                    c.outp[ob + 160000] = sg.z;
                    c.outp[ob + 240000] = sg.w;
                }
            }
        }
    }
    tb += NTASK;
}

// ---------------- GRU elementwise state update ----------------
__device__ __forceinline__ void gru_up(int j, int H, const float4* gi, const float4* pp,
                                       const float4* vv, const float4* hh, float4 pg0, float4* s) {
    float4 gr = add4(gi[j],         add4(mul4(pg0, pp[j]),         vv[j]));
    float4 gz = add4(gi[j + H],     add4(mul4(pg0, pp[j + H]),     vv[j + H]));
    float4 gn = add4(gi[j + 2 * H], add4(mul4(pg0, pp[j + 2 * H]), vv[j + 2 * H]));
    float4 r = sig4v(add4(gr, hh[j]));
    float4 z = sig4v(add4(gz, hh[j + H]));
    float4 n = tanh4v(add4(gn, mul4(r, hh[j + 2 * H])));
    float4 sv = s[j];
    s[j] = make_float4((1.f - z.x) * n.x + z.x * sv.x, (1.f - z.y) * n.y + z.y * sv.y,
                       (1.f - z.z) * n.z + z.z * sv.z, (1.f - z.w) * n.w + z.w * sv.w);
}

// ---------------- dynamic smem layout (float4 units) ----------------
#define O_XCAT  0
#define O_BT    328
#define O_FW    520
#define O_PG    712
#define O_HH1   716
#define O_HH2   1196
#define O_HH3   1580
#define O_PP1   1964
#define O_VV1   2444
#define O_PP2   2924
#define O_VV2   3308
#define O_PP3   3692
#define O_VV3   4076
#define O_PPS   4460
#define O_VVS   4588
#define O_GIF   4716
#define O_S1    5196
#define O_S2    5356
#define O_S3    5484
#define O_G1    5612
#define O_G2    5772
#define O_G3    5900
#define O_SKF   6028
#define O_SK1   6156
#define O_SK2   6284
#define O_BT2   6412
#define O_SKV   6540
#define N_F4    6668
#define SMEM_BYTES (N_F4 * 16 + (4 * 256 + 4 + 4) * 4)

// ---------------- persistent scan: each CTA owns 4 batch chains ----------------
__global__ __launch_bounds__(NT, 1) void k_scan(const int* __restrict__ period,
                                                const float* __restrict__ gout_b,
                                                float* __restrict__ out) {
    int b0 = blockIdx.x * BPC;
    extern __shared__ float4 sm4[];
    float4* xcat4 = sm4 + O_XCAT;
    float4* bt4   = sm4 + O_BT;
    float4* fw4   = sm4 + O_FW;
    float4* pg4   = sm4 + O_PG;
    float4* hh1   = sm4 + O_HH1;
    float4* hh2   = sm4 + O_HH2;
    float4* hh3   = sm4 + O_HH3;
    float4* pp1   = sm4 + O_PP1;
    float4* vv1   = sm4 + O_VV1;
    float4* pp2   = sm4 + O_PP2;
    float4* vv2   = sm4 + O_VV2;
    float4* pp3   = sm4 + O_PP3;
    float4* vv3   = sm4 + O_VV3;
    float4* pps   = sm4 + O_PPS;
    float4* vvs   = sm4 + O_VVS;
    float4* gif   = sm4 + O_GIF;
    float4* s1    = sm4 + O_S1;
    float4* s2    = sm4 + O_S2;
    float4* s3    = sm4 + O_S3;
    float4* g1    = sm4 + O_G1;
    float4* g2    = sm4 + O_G2;
    float4* g3    = sm4 + O_G3;
    float4* skf   = sm4 + O_SKF;
    float4* sk1   = sm4 + O_SK1;
    float4* sk2   = sm4 + O_SK2;
    float4* bt2   = sm4 + O_BT2;
    float4* skv4  = sm4 + O_SKV;
    float*  excp  = (float*)(sm4 + N_F4);
    float*  sgain = excp + 4 * 256;
    int*    sper  = (int*)(sgain + 4);
    int tid = threadIdx.x;
    const float* gw = g_wt;

    // init
    for (int i = tid; i < 4 * 256; i += NT) excp[i] = 0.0f;
    float4 z4 = make_float4(0.f, 0.f, 0.f, 0.f);
    for (int i = tid; i < 328; i += NT) xcat4[i] = z4;
    for (int i = tid; i < 160; i += NT) s1[i] = z4;
    for (int i = tid; i < 128; i += NT) s2[i] = z4;
    for (int i = tid; i < 128; i += NT) s3[i] = z4;
    __syncthreads();

    const float4* fpit = xcat4 + 164 + 82;   // fpitch (40)
    const float4* fprv = xcat4 + 164 + 124;  // prev   (40)

    Ctx c0 = {};
    c0.skf = skf; c0.sk1 = sk1; c0.sk2 = sk2; c0.skp = pps; c0.skv = vvs; c0.pgv = pg4;
    c0.bias = gout_b; c0.gain = sgain; c0.excp = excp; c0.outp = out; c0.b0 = b0;

    int base = 0;
    for (int s = 0; s < NSTEP; s++) {
        int frame = s >> 2, sub = s & 3;
        // P0a: scalars + state shift
        if (tid >= 504) {
            int u = tid - 504;
            if (u < 4) {
                int p = period[(b0 + u) * TT + 3 + frame];
                sper[u] = min(max(p, 32), 254);
            } else {
                sgain[u - 4] = g_gain[s * BATCH + b0 + (u - 4)];
            }
        }
        if (tid < 164) xcat4[tid] = xcat4[164 + tid];
        __syncthreads();
        // P0b: build tmp = [cond80 | pred44 | prev40]
        if (tid < 164) {
            int j = tid;
            float4 v;
            if (j < 80) {
                size_t cb = (size_t)sub * 80 + j;
                v.x = g_cond[((size_t)((b0 + 0) * TC + frame)) * 320 + cb];
                v.y = g_cond[((size_t)((b0 + 1) * TC + frame)) * 320 + cb];
                v.z = g_cond[((size_t)((b0 + 2) * TC + frame)) * 320 + cb];
                v.w = g_cond[((size_t)((b0 + 3) * TC + frame)) * 320 + cb];
            } else if (j < 124) {
                int i2 = j - 80;
                float vv_[4];
#pragma unroll
                for (int bb = 0; bb < 4; bb++) {
                    int idx = 254 - sper[bb] + i2;
                    if (idx >= 256) idx -= sper[bb];
                    idx = max(0, min(255, idx));
                    vv_[bb] = excp[bb * 256 + ((base + idx) & 255)] / (1e-5f + sgain[bb]);
                }
                v = make_float4(vv_[0], vv_[1], vv_[2], vv_[3]);
            } else {
                int i2 = j - 124;
                float vv_[4];
#pragma unroll
                for (int bb = 0; bb < 4; bb++) {
                    vv_[bb] = excp[bb * 256 + ((base + 216 + i2) & 255)] / (1e-5f + sgain[bb]);
                }
                v = make_float4(vv_[0], vv_[1], vv_[2], vv_[3]);
            }
            xcat4[164 + j] = v;
        }
        __syncthreads();

        // P1: fwc + g1hh + g2hh + pitch/prev projections (g1,g2)
        {
            int tb = 0;
            run_seg<328, 192, 1>(tb, gw + OFF_FWC, xcat4, bt4, 0, c0);
            run_seg<160, 480, 0>(tb, gw + OFF_G1HH, s1, hh1, 0, c0);
            run_seg<128, 384, 0>(tb, gw + OFF_G2HH, s2, hh2, 0, c0);
            run_seg<40, 480, 0>(tb, gw + OFF_G1P, fpit, pp1, 0, c0);
            run_seg<40, 480, 0>(tb, gw + OFF_G1V, fprv, vv1, 0, c0);
            run_seg<40, 384, 0>(tb, gw + OFF_G2P, fpit, pp2, 0, c0);
            run_seg<40, 384, 0>(tb, gw + OFF_G2V, fprv, vv2, 0, c0);
        }
        __syncthreads();

        // P2: fwcg (GLU -> fw4) + g3hh + pitch/prev (g3, skip)
        {
            int tb = 0;
            run_seg<192, 192, 2>(tb, gw + OFF_FWCG, bt4, fw4, bt4, c0);
            run_seg<128, 384, 0>(tb, gw + OFF_G3HH, s3, hh3, 0, c0);
            run_seg<40, 384, 0>(tb, gw + OFF_G3P, fpit, pp3, 0, c0);
            run_seg<40, 384, 0>(tb, gw + OFF_G3V, fprv, vv3, 0, c0);
            run_seg<40, 128, 0>(tb, gw + OFF_SKP, fpit, pps, 0, c0);
            run_seg<40, 128, 0>(tb, gw + OFF_SKV, fprv, vvs, 0, c0);
        }
        __syncthreads();

        // P3: gru1 ih-fwc part + skip fwc part + pg
        {
            int tb = 0;
            run_seg<192, 480, 0>(tb, gw + OFF_G1IH, fw4, gif, 0, c0);
            run_seg<192, 128, 0>(tb, gw + OFF_SKF, fw4, skf, 0, c0);
            run_seg<192, 4, 4>(tb, gw + OFF_GOUT, fw4, pg4, 0, c0);
        }
        __syncthreads();

        // E3: s1 update
        if (tid < 160) gru_up(tid, 160, gif, pp1, vv1, hh1, pg4[0], s1);
        __syncthreads();

        // P4: glu1
        { int tb = 0; run_seg<160, 160, 2>(tb, gw + OFF_GLU1, s1, g1, s1, c0); }
        __syncthreads();

        // P5: gru2 ih-g1 part + skip g1 part
        {
            int tb = 0;
            run_seg<160, 384, 0>(tb, gw + OFF_G2IH, g1, gif, 0, c0);
            run_seg<160, 128, 0>(tb, gw + OFF_SK1, g1, sk1, 0, c0);
        }
        __syncthreads();

        // E5: s2 update
        if (tid < 128) gru_up(tid, 128, gif, pp2, vv2, hh2, pg4[1], s2);
        __syncthreads();

        // P6: glu2
        { int tb = 0; run_seg<128, 128, 2>(tb, gw + OFF_GLU2, s2, g2, s2, c0); }
        __syncthreads();

        // P7: gru3 ih-g2 part + skip g2 part
        {
            int tb = 0;
            run_seg<128, 384, 0>(tb, gw + OFF_G3IH, g2, gif, 0, c0);
            run_seg<128, 128, 0>(tb, gw + OFF_SK2, g2, sk2, 0, c0);
        }
        __syncthreads();

        // E7: s3 update
        if (tid < 128) gru_up(tid, 128, gif, pp3, vv3, hh3, pg4[2], s3);
        __syncthreads();

        // P8: glu3
        { int tb = 0; run_seg<128, 128, 2>(tb, gw + OFF_GLU3, s3, g3, s3, c0); }
        __syncthreads();

        // P9: skip g3 part + full skip sum + tanh -> bt2
        { int tb = 0; run_seg<128, 128, 3>(tb, gw + OFF_SK3, g3, bt2, 0, c0); }
        __syncthreads();

        // P10: skip glu
        { int tb = 0; run_seg<128, 128, 2>(tb, gw + OFF_SKIPG, bt2, skv4, bt2, c0); }
        __syncthreads();

        // P11: sig matvec + tanh*gain + exc/out write
        c0.base = base; c0.step = s;
        { int tb = 0; run_seg<128, 40, 5>(tb, gw + OFF_SIG, skv4, bt2, 0, c0); }
        __syncthreads();
        base = (base + 40) & 255;
    }
}

// ---------------- launch ----------------
extern "C" void kernel_launch(void* const* d_in, const int* in_sizes, int n_in,
                              void* d_out, int out_size) {
    const float* features = (const float*)d_in[0];
    const int*   period   = (const int*)d_in[1];
    const float* pembed   = (const float*)d_in[2];
    const float* fd1_w    = (const float*)d_in[3];
    const float* fconv1_w = (const float*)d_in[4];
    const float* fd2_w    = (const float*)d_in[5];
    const float* cg_w     = (const float*)d_in[6];
    const float* cg_b     = (const float*)d_in[7];
    const float* gout_b   = (const float*)d_in[23];
    float* out = (float*)d_out;

    WP wp;
    for (int i = 0; i < 15; i++) wp.p[i] = (const float*)d_in[8 + i];

    cudaFuncSetAttribute(k_scan, cudaFuncAttributeMaxDynamicSharedMemorySize, SMEM_BYTES);

    dim3 tg((130560 + 255) / 256, 15);
    k_transpose_all<<<tg, 256>>>(wp);
    k_fd1<<<BATCH * TF, 64>>>(features, period, pembed, fd1_w);
    k_front<<<BATCH * TC, 320>>>(fconv1_w, fd2_w, cg_w, cg_b);
    k_scan<<<NCTA, NT, SMEM_BYTES>>>(period, gout_b, out);
    (void)in_sizes; (void)n_in; (void)out_size;
}

// round 7
// speedup vs baseline: 1.4025x; 1.4025x over previous
#include <cuda_runtime.h>
#include <math.h>
#include <stdint.h>

#define BATCH   128
#define TT      504
#define TF      502
#define TC      500
#define NSTEP   2000
#define NT      512
#define BPC     2
#define NCTA    (BATCH / BPC)

// ---------------- transposed-weight offsets (floats) ----------------
#define OFF_FWC    0          // (192,328)
#define OFF_FWCG   62976      // (192,192)
#define OFF_G1IH   99840      // (480,272)
#define OFF_G1HH   230400     // (480,160)
#define OFF_GLU1   307200     // (160,160)
#define OFF_G2IH   332800     // (384,240)
#define OFF_G2HH   424960     // (384,128)
#define OFF_GLU2   474112     // (128,128)
#define OFF_G3IH   490496     // (384,208)
#define OFF_G3HH   570368     // (384,128)
#define OFF_GLU3   619520     // (128,128)
#define OFF_SKIP   635904     // (128,688)
#define OFF_SKIPG  723968     // (128,128)
#define OFF_SIG    740352     // (40,128)
#define OFF_GOUT   745472     // (4,192)
#define WT_TOTAL   746240

// ---------------- device scratch ----------------
__device__ float g_x[BATCH * TF * 64];
__device__ float g_cond[BATCH * TC * 320];
__device__ float g_gain[NSTEP * BATCH];
__device__ float g_wt[WT_TOTAL];

__device__ __forceinline__ float sigf(float x) { return 1.0f / (1.0f + expf(-x)); }

typedef unsigned long long u64;
__device__ __forceinline__ void fma2(u64& d, u64 a, u64 b) {
    asm("fma.rn.f32x2 %0, %1, %2, %3;" : "=l"(d) : "l"(a), "l"(b), "l"(d));
}
__device__ __forceinline__ float2 upk(u64 v) {
    float2 r; asm("mov.b64 {%0, %1}, %2;" : "=f"(r.x), "=f"(r.y) : "l"(v)); return r;
}

// ---------------- fused weight transpose: Wt[k*out+o] = W[o*in+k] ----------------
struct WP { const float* p[15]; };
__constant__ int T_OFF[15] = {OFF_FWC, OFF_FWCG, OFF_G1IH, OFF_G1HH, OFF_GLU1,
                              OFF_G2IH, OFF_G2HH, OFF_GLU2, OFF_G3IH, OFF_G3HH,
                              OFF_GLU3, OFF_SKIP, OFF_SKIPG, OFF_SIG, OFF_GOUT};
__constant__ int T_OUT[15] = {192, 192, 480, 480, 160, 384, 384, 128, 384, 384, 128, 128, 128, 40, 4};
__constant__ int T_IN [15] = {328, 192, 272, 160, 160, 240, 128, 128, 208, 128, 128, 688, 128, 128, 192};

__global__ void k_transpose_all(WP wp) {
    int l = blockIdx.y;
    int i = blockIdx.x * blockDim.x + threadIdx.x;
    int out = T_OUT[l], in = T_IN[l];
    if (i < out * in) {
        int o = i / in, k = i - o * in;
        g_wt[T_OFF[l] + k * out + o] = wp.p[l][i];
    }
}

// ---------------- fd1 ----------------
__global__ void k_fd1(const float* __restrict__ feat, const int* __restrict__ period,
                      const float* __restrict__ pembed, const float* __restrict__ fd1) {
    int bt = blockIdx.x;
    int b = bt / TF, t = bt - b * TF;
    __shared__ float xin[32];
    int tid = threadIdx.x;
    if (tid < 20) {
        xin[tid] = feat[(b * TT + (t + 2)) * 20 + tid];
    } else if (tid < 32) {
        int per = period[b * TT + t + 2];
        per = min(max(per, 32), 254);
        xin[tid] = pembed[(per - 32) * 12 + (tid - 20)];
    }
    __syncthreads();
    float acc = 0.0f;
    const float* w = fd1 + tid * 32;
#pragma unroll
    for (int k = 0; k < 32; k++) acc += w[k] * xin[k];
    g_x[bt * 64 + tid] = tanhf(acc);
}

// ---------------- fused conv1d + fd2 + gain ----------------
__global__ void k_front(const float* __restrict__ wconv, const float* __restrict__ fd2,
                        const float* __restrict__ cg_w, const float* __restrict__ cg_b) {
    int bt = blockIdx.x;
    int b = bt / TC, t = bt - b * TC;
    __shared__ float xin[192];
    __shared__ float ybuf[128];
    __shared__ float condb[320];
    int tid = threadIdx.x;
    for (int i = tid; i < 192; i += 320) {
        xin[i] = g_x[(b * TF + t + (i >> 6)) * 64 + (i & 63)];
    }
    __syncthreads();
    if (tid < 128) {
        float acc = 0.0f;
        const float* w = wconv + tid * 192;
#pragma unroll 8
        for (int ic = 0; ic < 64; ic++) {
            acc += w[ic * 3 + 0] * xin[0 * 64 + ic];
            acc += w[ic * 3 + 1] * xin[1 * 64 + ic];
            acc += w[ic * 3 + 2] * xin[2 * 64 + ic];
        }
        ybuf[tid] = tanhf(acc);
    }
    __syncthreads();
    {
        float acc = 0.0f;
        const float* w = fd2 + tid * 128;
#pragma unroll 8
        for (int k = 0; k < 128; k++) acc += __ldg(w + k) * ybuf[k];
        float c = tanhf(acc);
        condb[tid] = c;
        g_cond[(size_t)bt * 320 + tid] = c;
    }
    __syncthreads();
    if (tid < 4) {
        float acc = cg_b[0];
        const float* c = condb + tid * 80;
#pragma unroll 8
        for (int k = 0; k < 80; k++) acc += cg_w[k] * c[k];
        float g = 0.2f + 0.8f * sigf(acc);
        g = fminf(fmaxf(g, 0.001f), 20.0f);
        g_gain[(t * 4 + tid) * BATCH + b] = g;
    }
}

// ---------------- matvec: weights as packed u64 pairs, x duplicated ----------------
// Wt [IN][OUT]; x0/x1: duplicated float2 arrays (v,v). DUP=1 -> write dup pairs to yA0/yA1.
// DUP=0 -> write plain float2 (b0,b1) to yA0. ACT: 0 none, 1 tanh.
template <int IN, int OUT, int ACT, int DUP>
__device__ __forceinline__ void mv(const float* __restrict__ Wt,
                                   const float2* __restrict__ x0,
                                   const float2* __restrict__ x1,
                                   float2* __restrict__ yA0, float2* __restrict__ yA1,
                                   float2* __restrict__ red0, float2* __restrict__ red1) {
    constexpr int RG = OUT / 4;
    constexpr int S0n = NT / RG;
    constexpr int S = (S0n > 32) ? 32 : S0n;
    const int tid = threadIdx.x;
    const int sl = tid / RG;
    const int rg = tid - sl * RG;
    if (sl < S) {
        u64 a0 = 0ull, a1 = 0ull, b0 = 0ull, b1 = 0ull;
        const ulonglong2* __restrict__ W2 = reinterpret_cast<const ulonglong2*>(Wt) + rg;
        const u64* __restrict__ xu0 = reinterpret_cast<const u64*>(x0);
        const u64* __restrict__ xu1 = reinterpret_cast<const u64*>(x1);
#pragma unroll 8
        for (int k = sl; k < IN; k += S) {
            ulonglong2 wv = __ldg(&W2[k * RG]);
            u64 xv0 = xu0[k];
            u64 xv1 = xu1[k];
            fma2(a0, wv.x, xv0); fma2(a1, wv.y, xv0);
            fma2(b0, wv.x, xv1); fma2(b1, wv.y, xv1);
        }
        int rb = sl * (OUT / 2) + rg * 2;
        red0[rb] = upk(a0); red0[rb + 1] = upk(a1);
        red1[rb] = upk(b0); red1[rb + 1] = upk(b1);
    }
    __syncthreads();
    for (int p = tid; p < OUT / 2; p += NT) {
        float2 t0 = make_float2(0.f, 0.f), t1 = make_float2(0.f, 0.f);
#pragma unroll
        for (int ss = 0; ss < S; ss++) {
            float2 v0 = red0[ss * (OUT / 2) + p];
            float2 v1 = red1[ss * (OUT / 2) + p];
            t0.x += v0.x; t0.y += v0.y; t1.x += v1.x; t1.y += v1.y;
        }
        if (ACT == 1) {
            t0.x = tanhf(t0.x); t0.y = tanhf(t0.y);
            t1.x = tanhf(t1.x); t1.y = tanhf(t1.y);
        }
        if (DUP) {
            yA0[2 * p]     = make_float2(t0.x, t0.x);
            yA0[2 * p + 1] = make_float2(t0.y, t0.y);
            yA1[2 * p]     = make_float2(t1.x, t1.x);
            yA1[2 * p + 1] = make_float2(t1.y, t1.y);
        } else {
            yA0[2 * p]     = make_float2(t0.x, t1.x);
            yA0[2 * p + 1] = make_float2(t0.y, t1.y);
        }
    }
    __syncthreads();
}

// ---------------- smem layout (float2 units) ----------------
#define O_RED0   0
#define O_RED1   1024
#define O_XC0    2048
#define O_XC1    2376
#define O_BT0    2704
#define O_BT1    2896
#define O_FW0    3088
#define O_FW1    3280
#define O_S10    3472
#define O_S11    3632
#define O_S20    3792
#define O_S21    3920
#define O_S30    4048
#define O_S31    4176
#define O_SKIN0  4304
#define O_SKIN1  4992
#define O_SKV0   5680
#define O_SKV1   5808
#define O_GI     5936
#define O_GH     6416
#define O_G1     6896
#define O_G2     7056
#define O_G3     7184
#define O_PG     7312
#define N_F2     7316
#define SMEM_BYTES (N_F2 * 8 + (2 * 256 + 2 + 2) * 4)

// ---------------- persistent scan: each CTA owns 2 batch chains ----------------
__global__ __launch_bounds__(NT, 1) void k_scan(const int* __restrict__ period,
                                                const float* __restrict__ gout_b,
                                                float* __restrict__ out) {
    int b0 = blockIdx.x * BPC;
    extern __shared__ float2 sm2[];
    float2* red0 = sm2 + O_RED0;
    float2* red1 = sm2 + O_RED1;
    float2* xc0  = sm2 + O_XC0;   // 328 dup, [0:164) state, [164:328) tmp
    float2* xc1  = sm2 + O_XC1;
    float2* bt0  = sm2 + O_BT0;   // 192 dup
    float2* bt1  = sm2 + O_BT1;
    float2* fw0  = sm2 + O_FW0;   // 192 dup
    float2* fw1  = sm2 + O_FW1;
    float2* s10  = sm2 + O_S10;   // 160 dup
    float2* s11  = sm2 + O_S11;
    float2* s20  = sm2 + O_S20;   // 128 dup
    float2* s21  = sm2 + O_S21;
    float2* s30  = sm2 + O_S30;   // 128 dup
    float2* s31  = sm2 + O_S31;
    float2* sk0  = sm2 + O_SKIN0; // 688 dup
    float2* sk1  = sm2 + O_SKIN1;
    float2* sv0  = sm2 + O_SKV0;  // 128 dup
    float2* sv1  = sm2 + O_SKV1;
    float2* gip  = sm2 + O_GI;    // 480 plain (b0,b1)
    float2* ghp  = sm2 + O_GH;    // 480 plain
    float2* g1p  = sm2 + O_G1;    // 160 plain
    float2* g2p  = sm2 + O_G2;    // 128 plain
    float2* g3p  = sm2 + O_G3;    // 128 plain
    float2* pgp  = sm2 + O_PG;    // 4 plain
    float*  excp = (float*)(sm2 + N_F2);  // 2*256
    float*  sgain = excp + 2 * 256;       // 2
    int*    sper  = (int*)(sgain + 2);    // 2
    int tid = threadIdx.x;
    const float* gw = g_wt;

    // init
    for (int i = tid; i < 2 * 256; i += NT) excp[i] = 0.0f;
    float2 z2 = make_float2(0.f, 0.f);
    for (int i = tid; i < 328; i += NT) { xc0[i] = z2; xc1[i] = z2; }
    for (int i = tid; i < 160; i += NT) { s10[i] = z2; s11[i] = z2; }
    for (int i = tid; i < 128; i += NT) { s20[i] = z2; s21[i] = z2; s30[i] = z2; s31[i] = z2; }
    __syncthreads();

    int base = 0;
    for (int s = 0; s < NSTEP; s++) {
        int frame = s >> 2, sub = s & 3;
        // P0a: scalars + state shift
        if (tid < 2) {
            int p = period[(b0 + tid) * TT + 3 + frame];
            sper[tid] = min(max(p, 32), 254);
        } else if (tid < 4) {
            sgain[tid - 2] = g_gain[s * BATCH + b0 + (tid - 2)];
        }
        for (int i = tid; i < 328; i += NT) {
            if (i < 164) xc0[i] = xc0[164 + i];
            else xc1[i - 164] = xc1[i];
        }
        __syncthreads();
        // P0b: build tmp = [cond80 | pred44 | prev40] for both batches
        if (tid < 164) {
            int j = tid;
            float v[2];
#pragma unroll
            for (int bb = 0; bb < 2; bb++) {
                float val;
                if (j < 80) {
                    val = g_cond[((size_t)((b0 + bb) * TC + frame)) * 320 + sub * 80 + j];
                } else if (j < 124) {
                    int i2 = j - 80;
                    int idx = 254 - sper[bb] + i2;
                    if (idx >= 256) idx -= sper[bb];
                    idx = max(0, min(255, idx));
                    val = excp[bb * 256 + ((base + idx) & 255)] / (1e-5f + sgain[bb]);
                } else {
                    val = excp[bb * 256 + ((base + 216 + (j - 124)) & 255)] / (1e-5f + sgain[bb]);
                }
                v[bb] = val;
            }
            xc0[164 + j] = make_float2(v[0], v[0]);
            xc1[164 + j] = make_float2(v[1], v[1]);
        }
        __syncthreads();

        // fwc: bt = tanh(fwc_w @ xcat)  (dup out: feeds fwcg)
        mv<328, 192, 1, 1>(gw + OFF_FWC, xc0, xc1, bt0, bt1, red0, red1);
        // fwcg: gh = fwc_glu @ bt  (plain)
        mv<192, 192, 0, 0>(gw + OFF_FWCG, bt0, bt1, ghp, 0, red0, red1);
        // fw = bt * sig(gh)  (dup)
        for (int i = tid; i < 2 * 192; i += NT) {
            int bb = i >= 192, j = bb ? i - 192 : i;
            float t = (bb ? bt1 : bt0)[j].x;
            float u = bb ? ghp[j].y : ghp[j].x;
            float vv = t * sigf(u);
            (bb ? fw1 : fw0)[j] = make_float2(vv, vv);
        }
        __syncthreads();

        // pg = sigmoid(gout @ fw + b)
        mv<192, 4, 0, 0>(gw + OFF_GOUT, fw0, fw1, pgp, 0, red0, red1);
        if (tid < 8) {
            int bb = tid >> 2, j = tid & 3;
            float* pf = (float*)pgp;
            pf[2 * j + bb] = sigf(pf[2 * j + bb] + gout_b[j]);
        }
        __syncthreads();

        // GRU1 input (272): [fw(192) | pg0*fpitch(40) | prev(40)]  (dup)
        for (int i = tid; i < 2 * 272; i += NT) {
            int bb = i >= 272, j = bb ? i - 272 : i;
            const float2* xcd = bb ? xc1 : xc0;
            float vv;
            if (j < 192) vv = (bb ? fw1 : fw0)[j].x;
            else if (j < 232) vv = (bb ? pgp[0].y : pgp[0].x) * xcd[164 + 82 + (j - 192)].x;
            else vv = xcd[164 + 124 + (j - 232)].x;
            (bb ? sk1 : sk0)[j] = make_float2(vv, vv);
        }
        __syncthreads();
        mv<272, 480, 0, 0>(gw + OFF_G1IH, sk0, sk1, gip, 0, red0, red1);
        mv<160, 480, 0, 0>(gw + OFF_G1HH, s10, s11, ghp, 0, red0, red1);
        // s1 update
        for (int i = tid; i < 2 * 160; i += NT) {
            int bb = i >= 160, j = bb ? i - 160 : i;
            const float* gif = (const float*)gip;
            const float* ghf = (const float*)ghp;
            float r = sigf(gif[2 * j + bb] + ghf[2 * j + bb]);
            float z = sigf(gif[2 * (160 + j) + bb] + ghf[2 * (160 + j) + bb]);
            float n = tanhf(gif[2 * (320 + j) + bb] + r * ghf[2 * (320 + j) + bb]);
            float2* sd = bb ? s11 : s10;
            float vv = (1.0f - z) * n + z * sd[j].x;
            sd[j] = make_float2(vv, vv);
        }
        __syncthreads();
        mv<160, 160, 0, 0>(gw + OFF_GLU1, s10, s11, ghp, 0, red0, red1);
        for (int i = tid; i < 2 * 160; i += NT) {
            int bb = i >= 160, j = bb ? i - 160 : i;
            float u = bb ? ghp[j].y : ghp[j].x;
            ((float*)g1p)[2 * j + bb] = (bb ? s11 : s10)[j].x * sigf(u);
        }
        __syncthreads();

        // GRU2 input (240): [g1(160) | pg1*fpitch | prev]
        for (int i = tid; i < 2 * 240; i += NT) {
            int bb = i >= 240, j = bb ? i - 240 : i;
            const float2* xcd = bb ? xc1 : xc0;
            float vv;
            if (j < 160) vv = bb ? g1p[j].y : g1p[j].x;
            else if (j < 200) vv = (bb ? pgp[1].y : pgp[1].x) * xcd[164 + 82 + (j - 160)].x;
            else vv = xcd[164 + 124 + (j - 200)].x;
            (bb ? sk1 : sk0)[j] = make_float2(vv, vv);
        }
        __syncthreads();
        mv<240, 384, 0, 0>(gw + OFF_G2IH, sk0, sk1, gip, 0, red0, red1);
        mv<128, 384, 0, 0>(gw + OFF_G2HH, s20, s21, ghp, 0, red0, red1);
        for (int i = tid; i < 2 * 128; i += NT) {
            int bb = i >= 128, j = bb ? i - 128 : i;
            const float* gif = (const float*)gip;
            const float* ghf = (const float*)ghp;
            float r = sigf(gif[2 * j + bb] + ghf[2 * j + bb]);
            float z = sigf(gif[2 * (128 + j) + bb] + ghf[2 * (128 + j) + bb]);
            float n = tanhf(gif[2 * (256 + j) + bb] + r * ghf[2 * (256 + j) + bb]);
            float2* sd = bb ? s21 : s20;
            float vv = (1.0f - z) * n + z * sd[j].x;
            sd[j] = make_float2(vv, vv);
        }
        __syncthreads();
        mv<128, 128, 0, 0>(gw + OFF_GLU2, s20, s21, ghp, 0, red0, red1);
        for (int i = tid; i < 2 * 128; i += NT) {
            int bb = i >= 128, j = bb ? i - 128 : i;
            float u = bb ? ghp[j].y : ghp[j].x;
            ((float*)g2p)[2 * j + bb] = (bb ? s21 : s20)[j].x * sigf(u);
        }
        __syncthreads();

        // GRU3 input (208): [g2(128) | pg2*fpitch | prev]
        for (int i = tid; i < 2 * 208; i += NT) {
            int bb = i >= 208, j = bb ? i - 208 : i;
            const float2* xcd = bb ? xc1 : xc0;
            float vv;
            if (j < 128) vv = bb ? g2p[j].y : g2p[j].x;
            else if (j < 168) vv = (bb ? pgp[2].y : pgp[2].x) * xcd[164 + 82 + (j - 128)].x;
            else vv = xcd[164 + 124 + (j - 168)].x;
            (bb ? sk1 : sk0)[j] = make_float2(vv, vv);
        }
        __syncthreads();
        mv<208, 384, 0, 0>(gw + OFF_G3IH, sk0, sk1, gip, 0, red0, red1);
        mv<128, 384, 0, 0>(gw + OFF_G3HH, s30, s31, ghp, 0, red0, red1);
        for (int i = tid; i < 2 * 128; i += NT) {
            int bb = i >= 128, j = bb ? i - 128 : i;
            const float* gif = (const float*)gip;
            const float* ghf = (const float*)ghp;
            float r = sigf(gif[2 * j + bb] + ghf[2 * j + bb]);
            float z = sigf(gif[2 * (128 + j) + bb] + ghf[2 * (128 + j) + bb]);
            float n = tanhf(gif[2 * (256 + j) + bb] + r * ghf[2 * (256 + j) + bb]);
            float2* sd = bb ? s31 : s30;
            float vv = (1.0f - z) * n + z * sd[j].x;
            sd[j] = make_float2(vv, vv);
        }
        __syncthreads();
        mv<128, 128, 0, 0>(gw + OFF_GLU3, s30, s31, ghp, 0, red0, red1);
        for (int i = tid; i < 2 * 128; i += NT) {
            int bb = i >= 128, j = bb ? i - 128 : i;
            float u = bb ? ghp[j].y : ghp[j].x;
            ((float*)g3p)[2 * j + bb] = (bb ? s31 : s30)[j].x * sigf(u);
        }
        __syncthreads();

        // skip_in (688): [g1 | g2 | g3 | fw | pg3*fpitch | prev]
        for (int i = tid; i < 2 * 688; i += NT) {
            int bb = i >= 688, j = bb ? i - 688 : i;
            const float2* xcd = bb ? xc1 : xc0;
            float vv;
            if (j < 160) vv = bb ? g1p[j].y : g1p[j].x;
            else if (j < 288) vv = bb ? g2p[j - 160].y : g2p[j - 160].x;
            else if (j < 416) vv = bb ? g3p[j - 288].y : g3p[j - 288].x;
            else if (j < 608) vv = (bb ? fw1 : fw0)[j - 416].x;
            else if (j < 648) vv = (bb ? pgp[3].y : pgp[3].x) * xcd[164 + 82 + (j - 608)].x;
            else vv = xcd[164 + 124 + (j - 648)].x;
            (bb ? sk1 : sk0)[j] = make_float2(vv, vv);
        }
        __syncthreads();
        mv<688, 128, 1, 1>(gw + OFF_SKIP, sk0, sk1, bt0, bt1, red0, red1);
        mv<128, 128, 0, 0>(gw + OFF_SKIPG, bt0, bt1, ghp, 0, red0, red1);
        for (int i = tid; i < 2 * 128; i += NT) {
            int bb = i >= 128, j = bb ? i - 128 : i;
            float u = bb ? ghp[j].y : ghp[j].x;
            float vv = (bb ? bt1 : bt0)[j].x * sigf(u);
            (bb ? sv1 : sv0)[j] = make_float2(vv, vv);
        }
        __syncthreads();

        // sig = tanh(sig_w @ skv) * gain -> exc push + output
        mv<128, 40, 1, 0>(gw + OFF_SIG, sv0, sv1, gip, 0, red0, red1);
        if (tid < 80) {
            int bb = tid >= 40, j = bb ? tid - 40 : tid;
            float vv = (bb ? gip[j].y : gip[j].x) * sgain[bb];
            excp[bb * 256 + ((base + j) & 255)] = vv;
            out[(size_t)(b0 + bb) * 80000 + (size_t)s * 40 + j] = vv;
        }
        __syncthreads();
        base = (base + 40) & 255;
    }
}

// ---------------- launch ----------------
extern "C" void kernel_launch(void* const* d_in, const int* in_sizes, int n_in,
                              void* d_out, int out_size) {
    const float* features = (const float*)d_in[0];
    const int*   period   = (const int*)d_in[1];
    const float* pembed   = (const float*)d_in[2];
    const float* fd1_w    = (const float*)d_in[3];
    const float* fconv1_w = (const float*)d_in[4];
    const float* fd2_w    = (const float*)d_in[5];
    const float* cg_w     = (const float*)d_in[6];
    const float* cg_b     = (const float*)d_in[7];
    const float* gout_b   = (const float*)d_in[23];
    float* out = (float*)d_out;

    WP wp;
    for (int i = 0; i < 15; i++) wp.p[i] = (const float*)d_in[8 + i];

    cudaFuncSetAttribute(k_scan, cudaFuncAttributeMaxDynamicSharedMemorySize, SMEM_BYTES);

    dim3 tg((130560 + 255) / 256, 15);
    k_transpose_all<<<tg, 256>>>(wp);
    k_fd1<<<BATCH * TF, 64>>>(features, period, pembed, fd1_w);
    k_front<<<BATCH * TC, 320>>>(fconv1_w, fd2_w, cg_w, cg_b);
    k_scan<<<NCTA, NT, SMEM_BYTES>>>(period, gout_b, out);
    (void)in_sizes; (void)n_in; (void)out_size;
}